// round 1
// baseline (speedup 1.0000x reference)
#include <cuda_runtime.h>
#include <cuda_bf16.h>

// Problem constants (fixed by the reference)
#define NVOX   131072
#define KVOL   27
#define PPK    65536
#define CIN    64
#define COUT   64
#define TILE_P 128
#define NTHREADS 256

// ---------------------------------------------------------------------------
// Vector float4 reduction to global memory (no return value). sm_90+.
// ---------------------------------------------------------------------------
__device__ __forceinline__ void red_add_v4(float* addr, float a, float b, float c, float d) {
    asm volatile("red.global.add.v4.f32 [%0], {%1, %2, %3, %4};"
                 :: "l"(addr), "f"(a), "f"(b), "f"(c), "f"(d)
                 : "memory");
}

// ---------------------------------------------------------------------------
// Kernel 1: initialize output with broadcast bias. out[n][c] = bias[c].
// Grid covers N*COUT/4 float4 elements.
// ---------------------------------------------------------------------------
__global__ void init_bias_kernel(float4* __restrict__ out, const float4* __restrict__ bias) {
    int i = blockIdx.x * blockDim.x + threadIdx.x;
    // row stride is 64 floats = 16 float4 chunks; chunk index within row = i % 16
    out[i] = bias[i & 15];
}

// ---------------------------------------------------------------------------
// Kernel 2: one block per (kernel offset, 128-pair tile).
//   - stage W[k] (64x64 fp32) and gathered A^T (cin-major, 64x128) in smem
//   - 4 (pairs) x 8 (couts) register tile per thread, 256 threads
//   - scatter-add via red.global.add.v4.f32
// ---------------------------------------------------------------------------
__global__ __launch_bounds__(NTHREADS) void conv3d_gemm_kernel(
    const float* __restrict__ in_feats,   // [NVOX, CIN]
    const float* __restrict__ weights,    // [KVOL, CIN, COUT]
    const int*   __restrict__ imap,       // [KVOL, PPK]
    const int*   __restrict__ omap,       // [KVOL, PPK]
    float*       __restrict__ out)        // [NVOX, COUT]
{
    __shared__ float Ws[CIN][COUT];       // 16 KB
    __shared__ float As[CIN][TILE_P];     // 32 KB, transposed gathered tile
    __shared__ int   orow[TILE_P];

    const int k   = blockIdx.y;
    const int p0  = blockIdx.x * TILE_P;
    const int tid = threadIdx.x;

    // ---- load weight tile (4096 floats, coalesced float4) ----
    {
        const float4* wsrc = (const float4*)(weights + (size_t)k * CIN * COUT);
        float4* wdst = (float4*)&Ws[0][0];
        #pragma unroll
        for (int i = 0; i < 4; i++)
            wdst[tid + i * NTHREADS] = wsrc[tid + i * NTHREADS];
    }

    // ---- load omap rows for this tile ----
    if (tid < TILE_P)
        orow[tid] = omap[k * PPK + p0 + tid];

    // ---- gather input rows, write transposed into As ----
    // 2 threads per row; each thread covers 32 cin values (8 float4 loads)
    {
        const int r    = tid >> 1;      // 0..127
        const int half = tid & 1;       // 0/1
        const int in_row = imap[k * PPK + p0 + r];
        const float4* src = (const float4*)(in_feats + (size_t)in_row * CIN + half * 32);
        #pragma unroll
        for (int q = 0; q < 8; q++) {
            float4 v = src[q];
            const int cin = half * 32 + q * 4;
            As[cin + 0][r] = v.x;
            As[cin + 1][r] = v.y;
            As[cin + 2][r] = v.z;
            As[cin + 3][r] = v.w;
        }
    }
    __syncthreads();

    // ---- register-tiled GEMM: 4 pairs x 8 couts per thread ----
    const int tx = tid & 31;   // pair group: pairs 4*tx .. 4*tx+3 (warp spans pairs)
    const int ty = tid >> 5;   // cout group: couts 8*ty .. 8*ty+7 (uniform per warp)

    float acc[4][8];
    #pragma unroll
    for (int i = 0; i < 4; i++)
        #pragma unroll
        for (int j = 0; j < 8; j++)
            acc[i][j] = 0.0f;

    #pragma unroll 16
    for (int kk = 0; kk < CIN; kk++) {
        // A: 128B contiguous per warp -> conflict-free LDS.128
        float4 a  = *(const float4*)&As[kk][tx * 4];
        // W: warp-uniform addresses -> broadcast
        float4 w0 = *(const float4*)&Ws[kk][ty * 8];
        float4 w1 = *(const float4*)&Ws[kk][ty * 8 + 4];

        float av[4] = {a.x, a.y, a.z, a.w};
        float wv[8] = {w0.x, w0.y, w0.z, w0.w, w1.x, w1.y, w1.z, w1.w};

        #pragma unroll
        for (int i = 0; i < 4; i++)
            #pragma unroll
            for (int j = 0; j < 8; j++)
                acc[i][j] = fmaf(av[i], wv[j], acc[i][j]);
    }

    // ---- scatter-add epilogue: 2 x red.v4 per owned pair row ----
    #pragma unroll
    for (int i = 0; i < 4; i++) {
        const int row = orow[tx * 4 + i];
        float* dst = out + (size_t)row * COUT + ty * 8;
        red_add_v4(dst,     acc[i][0], acc[i][1], acc[i][2], acc[i][3]);
        red_add_v4(dst + 4, acc[i][4], acc[i][5], acc[i][6], acc[i][7]);
    }
}

// ---------------------------------------------------------------------------
// Launch: init bias, then 27 x 512 GEMM-scatter blocks.
// ---------------------------------------------------------------------------
extern "C" void kernel_launch(void* const* d_in, const int* in_sizes, int n_in,
                              void* d_out, int out_size) {
    const float* in_feats = (const float*)d_in[0];
    const float* weights  = (const float*)d_in[1];
    const float* bias     = (const float*)d_in[2];
    const int*   imap     = (const int*)d_in[3];
    const int*   omap     = (const int*)d_in[4];
    float*       out      = (float*)d_out;

    // init output with bias: N*COUT/4 float4
    {
        const int total4 = NVOX * COUT / 4;
        init_bias_kernel<<<total4 / NTHREADS, NTHREADS>>>((float4*)out, (const float4*)bias);
    }

    dim3 grid(PPK / TILE_P, KVOL);
    conv3d_gemm_kernel<<<grid, NTHREADS>>>(in_feats, weights, imap, omap, out);
}

// round 2
// speedup vs baseline: 1.1277x; 1.1277x over previous
#include <cuda_runtime.h>
#include <cuda_bf16.h>

// Problem constants (fixed by the reference)
#define NVOX   131072
#define KVOL   27
#define PPK    65536
#define CIN    64
#define COUT   64
#define TILE_P 128
#define NTHREADS 128

// ---------------------------------------------------------------------------
// Packed fp32x2 helpers (sm_103a dual-rate FMA pipe; exact fp32 math)
// ---------------------------------------------------------------------------
#define FMA_F32X2(d, a, b) \
    asm("fma.rn.f32x2 %0, %1, %2, %3;" : "=l"(d) : "l"(a), "l"(b), "l"(d))

#define PACK_DUP_F32X2(out, v) \
    asm("mov.b64 %0, {%1, %1};" : "=l"(out) : "r"(__float_as_uint(v)))

#define UNPACK_F32X2(lo, hi, in) \
    asm("mov.b64 {%0, %1}, %2;" : "=f"(lo), "=f"(hi) : "l"(in))

__device__ __forceinline__ void red_add_v4(float* addr, float a, float b, float c, float d) {
    asm volatile("red.global.add.v4.f32 [%0], {%1, %2, %3, %4};"
                 :: "l"(addr), "f"(a), "f"(b), "f"(c), "f"(d)
                 : "memory");
}

// ---------------------------------------------------------------------------
// Kernel 1: out[n][c] = bias[c]
// ---------------------------------------------------------------------------
__global__ void init_bias_kernel(float4* __restrict__ out, const float4* __restrict__ bias) {
    int i = blockIdx.x * blockDim.x + threadIdx.x;
    out[i] = bias[i & 15];
}

// ---------------------------------------------------------------------------
// Kernel 2: one block per (kernel offset, 128-pair tile).
//   128 threads, 8 pairs x 8 couts register tile, packed f32x2 FMA,
//   conflict-free transpose gather, red.v4 scatter epilogue.
// ---------------------------------------------------------------------------
__global__ __launch_bounds__(NTHREADS, 4) void conv3d_gemm_kernel(
    const float* __restrict__ in_feats,   // [NVOX, CIN]
    const float* __restrict__ weights,    // [KVOL, CIN, COUT]
    const int*   __restrict__ imap,       // [KVOL, PPK]
    const int*   __restrict__ omap,       // [KVOL, PPK]
    float*       __restrict__ out)        // [NVOX, COUT]
{
    __shared__ float Ws[CIN][COUT];       // 16 KB
    __shared__ float As[CIN][TILE_P];     // 32 KB (transposed gathered tile)

    const int k   = blockIdx.y;
    const int p0  = blockIdx.x * TILE_P;
    const int tid = threadIdx.x;

    // ---- weight tile: 1024 float4, 8 per thread, coalesced ----
    {
        const float4* wsrc = (const float4*)(weights + (size_t)k * CIN * COUT);
        float4* wdst = (float4*)&Ws[0][0];
        #pragma unroll
        for (int i = 0; i < 8; i++)
            wdst[tid + i * NTHREADS] = wsrc[tid + i * NTHREADS];
    }

    // ---- gather: 1 thread per pair-row; transpose store is conflict-free
    //      (lane -> column r, bank = r % 32, all distinct within warp) ----
    {
        const int r = tid;                 // 0..127
        const int in_row = imap[k * PPK + p0 + r];
        const float4* src = (const float4*)(in_feats + (size_t)in_row * CIN);
        #pragma unroll
        for (int q = 0; q < 16; q++) {
            float4 v = src[q];
            const int cin = q * 4;
            As[cin + 0][r] = v.x;
            As[cin + 1][r] = v.y;
            As[cin + 2][r] = v.z;
            As[cin + 3][r] = v.w;
        }
    }
    __syncthreads();

    // ---- register-tiled GEMM: 8 pairs x 8 couts per thread, f32x2 packed ----
    // Thread's pairs: {4*tx .. 4*tx+3} and {64+4*tx .. 64+4*tx+3}  (tx = 0..15)
    //   -> LDS.128 lane stride of 4 words: conflict-free, ty-duplicates broadcast.
    // Thread's couts: 8*ty .. 8*ty+7  (ty = 0..7)
    const int tx = tid & 15;
    const int ty = tid >> 4;

    unsigned long long acc[8][4];   // [pair][cout-pair], f32x2 packed over couts
    #pragma unroll
    for (int i = 0; i < 8; i++)
        #pragma unroll
        for (int j = 0; j < 4; j++)
            acc[i][j] = 0ULL;

    #pragma unroll 4
    for (int kk = 0; kk < CIN; kk++) {
        float4 a0 = *(const float4*)&As[kk][tx * 4];
        float4 a1 = *(const float4*)&As[kk][64 + tx * 4];
        // W as native f32x2 pairs (no packing cost), warp has 2 unique addrs -> broadcast
        ulonglong2 w01 = *(const ulonglong2*)&Ws[kk][ty * 8];
        ulonglong2 w23 = *(const ulonglong2*)&Ws[kk][ty * 8 + 4];
        unsigned long long wp[4] = {w01.x, w01.y, w23.x, w23.y};

        float av[8] = {a0.x, a0.y, a0.z, a0.w, a1.x, a1.y, a1.z, a1.w};
        unsigned long long ad[8];
        #pragma unroll
        for (int i = 0; i < 8; i++)
            PACK_DUP_F32X2(ad[i], av[i]);

        #pragma unroll
        for (int i = 0; i < 8; i++)
            #pragma unroll
            for (int j = 0; j < 4; j++)
                FMA_F32X2(acc[i][j], ad[i], wp[j]);
    }

    // ---- scatter-add epilogue ----
    const int obase = k * PPK + p0;
    #pragma unroll
    for (int i = 0; i < 8; i++) {
        const int r = (i < 4) ? (tx * 4 + i) : (64 + tx * 4 + (i - 4));
        const int row = __ldg(omap + obase + r);
        float f[8];
        #pragma unroll
        for (int j = 0; j < 4; j++)
            UNPACK_F32X2(f[2 * j], f[2 * j + 1], acc[i][j]);
        float* dst = out + (size_t)row * COUT + ty * 8;
        red_add_v4(dst,     f[0], f[1], f[2], f[3]);
        red_add_v4(dst + 4, f[4], f[5], f[6], f[7]);
    }
}

// ---------------------------------------------------------------------------
extern "C" void kernel_launch(void* const* d_in, const int* in_sizes, int n_in,
                              void* d_out, int out_size) {
    const float* in_feats = (const float*)d_in[0];
    const float* weights  = (const float*)d_in[1];
    const float* bias     = (const float*)d_in[2];
    const int*   imap     = (const int*)d_in[3];
    const int*   omap     = (const int*)d_in[4];
    float*       out      = (float*)d_out;

    {
        const int total4 = NVOX * COUT / 4;
        init_bias_kernel<<<total4 / 256, 256>>>((float4*)out, (const float4*)bias);
    }

    dim3 grid(PPK / TILE_P, KVOL);
    conv3d_gemm_kernel<<<grid, NTHREADS>>>(in_feats, weights, imap, omap, out);
}

// round 3
// speedup vs baseline: 1.2052x; 1.0687x over previous
#include <cuda_runtime.h>
#include <cuda_bf16.h>

// Problem constants (fixed by the reference)
#define NVOX   131072
#define KVOL   27
#define PPK    65536
#define CIN    64
#define COUT   64
#define TILE_P 128
#define NTHREADS 128

// Column swizzle for the transposed A tile:
//   phys_col(r, cin) = r ^ F(cin),  F(c) = (c & 28) ^ ((c & 32) >> 1)
// - F has low 2 bits clear -> 4-consecutive-r float4 groups stay contiguous
// - F takes 16 distinct values over cin/4 = 0..15 -> store lanes hit 32 banks
#define SWZ(c) (((c) & 28) ^ (((c) & 32) >> 1))

// ---------------------------------------------------------------------------
// Packed fp32x2 helpers (dual-rate FMA pipe; exact fp32 math)
// ---------------------------------------------------------------------------
#define FMA_F32X2(d, a, b) \
    asm("fma.rn.f32x2 %0, %1, %2, %3;" : "=l"(d) : "l"(a), "l"(b), "l"(d))

#define PACK_DUP_F32X2(out, v) \
    asm("mov.b64 %0, {%1, %1};" : "=l"(out) : "r"(__float_as_uint(v)))

#define UNPACK_F32X2(lo, hi, in) \
    asm("mov.b64 {%0, %1}, %2;" : "=f"(lo), "=f"(hi) : "l"(in))

__device__ __forceinline__ void red_add_v4(float* addr, float a, float b, float c, float d) {
    asm volatile("red.global.add.v4.f32 [%0], {%1, %2, %3, %4};"
                 :: "l"(addr), "f"(a), "f"(b), "f"(c), "f"(d)
                 : "memory");
}

// ---------------------------------------------------------------------------
// Kernel 1: out[n][c] = bias[c]
// ---------------------------------------------------------------------------
__global__ void init_bias_kernel(float4* __restrict__ out, const float4* __restrict__ bias) {
    int i = blockIdx.x * blockDim.x + threadIdx.x;
    out[i] = bias[i & 15];
}

// ---------------------------------------------------------------------------
// Kernel 2: one block per (kernel offset, 128-pair tile).
//   - coalesced gather: 16 lanes per input row (full-line LDG.128)
//   - swizzled transpose store (conflict-free STS + conflict-free LDS.128)
//   - 8 pairs x 8 couts register tile, packed f32x2 FMA
//   - red.v4 scatter epilogue
// ---------------------------------------------------------------------------
__global__ __launch_bounds__(NTHREADS, 4) void conv3d_gemm_kernel(
    const float* __restrict__ in_feats,   // [NVOX, CIN]
    const float* __restrict__ weights,    // [KVOL, CIN, COUT]
    const int*   __restrict__ imap,       // [KVOL, PPK]
    const int*   __restrict__ omap,       // [KVOL, PPK]
    float*       __restrict__ out)        // [NVOX, COUT]
{
    __shared__ float Ws[CIN][COUT];       // 16 KB
    __shared__ float As[CIN][TILE_P];     // 32 KB, As[kk][r ^ SWZ(kk)]

    const int k   = blockIdx.y;
    const int p0  = blockIdx.x * TILE_P;
    const int tid = threadIdx.x;
    const int w   = tid >> 5;             // warp 0..3
    const int l   = tid & 31;             // lane

    // ---- weight tile: 1024 float4, 8 per thread, coalesced ----
    {
        const float4* wsrc = (const float4*)(weights + (size_t)k * CIN * COUT);
        float4* wdst = (float4*)&Ws[0][0];
        #pragma unroll
        for (int i = 0; i < 8; i++)
            wdst[tid + i * NTHREADS] = wsrc[tid + i * NTHREADS];
    }

    // ---- coalesced gather: warp w owns rows [32w, 32w+32) ----
    // Each LDG.128 instruction: 16 lanes per row x 16B = 2 complete rows,
    // perfect 128B-line utilization (4 wavefronts for 512B).
    {
        const int myidx = imap[k * PPK + p0 + w * 32 + l];  // row index held per lane
        const int c16 = l & 15;            // which float4 within the row
        const int rl  = l >> 4;            // 0/1: which of the 2 rows this instr
        const int cin = c16 * 4;
        const int fsw = SWZ(cin);          // same for all 4 cins in this float4

        #pragma unroll
        for (int q = 0; q < 16; q++) {
            const int src_row = __shfl_sync(0xffffffffu, myidx, 2 * q + rl);
            const int r = w * 32 + 2 * q + rl;
            float4 v = *(const float4*)(in_feats + (size_t)src_row * CIN + cin);
            const int pc = r ^ fsw;
            As[cin + 0][pc] = v.x;
            As[cin + 1][pc] = v.y;
            As[cin + 2][pc] = v.z;
            As[cin + 3][pc] = v.w;
        }
    }
    __syncthreads();

    // ---- register-tiled GEMM: 8 pairs x 8 couts per thread, f32x2 packed ----
    const int tx = tid & 15;
    const int ty = tid >> 4;

    unsigned long long acc[8][4];
    #pragma unroll
    for (int i = 0; i < 8; i++)
        #pragma unroll
        for (int j = 0; j < 4; j++)
            acc[i][j] = 0ULL;

    #pragma unroll 4
    for (int kk = 0; kk < CIN; kk++) {
        const int fsw = SWZ(kk);
        // swizzled reads: (4tx + i) ^ fsw = (4tx ^ fsw) + i  (fsw low2 = 0)
        float4 a0 = *(const float4*)&As[kk][(tx * 4) ^ fsw];
        float4 a1 = *(const float4*)&As[kk][(64 + tx * 4) ^ fsw];
        ulonglong2 w01 = *(const ulonglong2*)&Ws[kk][ty * 8];
        ulonglong2 w23 = *(const ulonglong2*)&Ws[kk][ty * 8 + 4];
        unsigned long long wp[4] = {w01.x, w01.y, w23.x, w23.y};

        float av[8] = {a0.x, a0.y, a0.z, a0.w, a1.x, a1.y, a1.z, a1.w};
        unsigned long long ad[8];
        #pragma unroll
        for (int i = 0; i < 8; i++)
            PACK_DUP_F32X2(ad[i], av[i]);

        #pragma unroll
        for (int i = 0; i < 8; i++)
            #pragma unroll
            for (int j = 0; j < 4; j++)
                FMA_F32X2(acc[i][j], ad[i], wp[j]);
    }

    // ---- scatter-add epilogue ----
    const int obase = k * PPK + p0;
    #pragma unroll
    for (int i = 0; i < 8; i++) {
        const int r = (i < 4) ? (tx * 4 + i) : (64 + tx * 4 + (i - 4));
        const int row = __ldg(omap + obase + r);
        float f[8];
        #pragma unroll
        for (int j = 0; j < 4; j++)
            UNPACK_F32X2(f[2 * j], f[2 * j + 1], acc[i][j]);
        float* dst = out + (size_t)row * COUT + ty * 8;
        red_add_v4(dst,     f[0], f[1], f[2], f[3]);
        red_add_v4(dst + 4, f[4], f[5], f[6], f[7]);
    }
}

// ---------------------------------------------------------------------------
extern "C" void kernel_launch(void* const* d_in, const int* in_sizes, int n_in,
                              void* d_out, int out_size) {
    const float* in_feats = (const float*)d_in[0];
    const float* weights  = (const float*)d_in[1];
    const float* bias     = (const float*)d_in[2];
    const int*   imap     = (const int*)d_in[3];
    const int*   omap     = (const int*)d_in[4];
    float*       out      = (float*)d_out;

    {
        const int total4 = NVOX * COUT / 4;
        init_bias_kernel<<<total4 / 256, 256>>>((float4*)out, (const float4*)bias);
    }

    dim3 grid(PPK / TILE_P, KVOL);
    conv3d_gemm_kernel<<<grid, NTHREADS>>>(in_feats, weights, imap, omap, out);
}

// round 4
// speedup vs baseline: 1.4458x; 1.1996x over previous
#include <cuda_runtime.h>
#include <cuda_bf16.h>

// Problem constants (fixed by the reference)
#define NVOX   131072
#define KVOL   27
#define PPK    65536
#define CIN    64
#define COUT   64
#define TILE_P 128
#define NTHREADS 128

// Column swizzle for the transposed A tile:
//   phys_col(r, cin) = r ^ F(cin),  F(c) = (c & 28) ^ ((c & 32) >> 1)
#define SWZ(c) (((c) & 28) ^ (((c) & 32) >> 1))

// Float4-group swizzle for the W tile: makes the 8 stride-8-word lane
// addresses (ty*8) bank-distinct. g = cout>>2 in 0..15.
#define WSWZ(g) ((g) ^ (((g) & 8) >> 3))

// ---------------------------------------------------------------------------
// Packed fp32x2 helpers (dual-rate FMA pipe; exact fp32 math)
// ---------------------------------------------------------------------------
#define FMA_F32X2(d, a, b) \
    asm("fma.rn.f32x2 %0, %1, %2, %3;" : "=l"(d) : "l"(a), "l"(b), "l"(d))

#define PACK_DUP_F32X2(out, v) \
    asm("mov.b64 %0, {%1, %1};" : "=l"(out) : "r"(__float_as_uint(v)))

#define UNPACK_F32X2(lo, hi, in) \
    asm("mov.b64 {%0, %1}, %2;" : "=f"(lo), "=f"(hi) : "l"(in))

__device__ __forceinline__ void red_add_v4(float* addr, float a, float b, float c, float d) {
    asm volatile("red.global.add.v4.f32 [%0], {%1, %2, %3, %4};"
                 :: "l"(addr), "f"(a), "f"(b), "f"(c), "f"(d)
                 : "memory");
}

// ---------------------------------------------------------------------------
// Kernel 1: out[n][c] = bias[c]
// ---------------------------------------------------------------------------
__global__ void init_bias_kernel(float4* __restrict__ out, const float4* __restrict__ bias) {
    int i = blockIdx.x * blockDim.x + threadIdx.x;
    out[i] = bias[i & 15];
}

// ---------------------------------------------------------------------------
// Kernel 2: one block per (kernel offset, 128-pair tile).
//   - coalesced gather (16 lanes per 256B input row), swizzled transpose STS
//   - 8 pairs x 8 couts register tile, packed f32x2 FMA
//   - warp-local row grouping: tx = tid>>3, ty = tid&7 so each red.v4
//     warp-instruction touches only 4 output rows (8 lines, not 32)
// ---------------------------------------------------------------------------
__global__ __launch_bounds__(NTHREADS, 4) void conv3d_gemm_kernel(
    const float* __restrict__ in_feats,   // [NVOX, CIN]
    const float* __restrict__ weights,    // [KVOL, CIN, COUT]
    const int*   __restrict__ imap,       // [KVOL, PPK]
    const int*   __restrict__ omap,       // [KVOL, PPK]
    float*       __restrict__ out)        // [NVOX, COUT]
{
    __shared__ float Ws[CIN][COUT];       // 16 KB, group-swizzled columns
    __shared__ float As[CIN][TILE_P];     // 32 KB, As[kk][r ^ SWZ(kk)]

    const int k   = blockIdx.y;
    const int p0  = blockIdx.x * TILE_P;
    const int tid = threadIdx.x;
    const int w   = tid >> 5;             // warp 0..3
    const int l   = tid & 31;             // lane

    // ---- weight tile: 1024 float4, 8 per thread, group-swizzled store ----
    {
        const float4* wsrc = (const float4*)(weights + (size_t)k * CIN * COUT);
        #pragma unroll
        for (int i = 0; i < 8; i++) {
            const int f4 = tid + i * NTHREADS;    // linear float4 index
            const int kk = f4 >> 4;
            const int g  = f4 & 15;
            *(float4*)&Ws[kk][WSWZ(g) * 4] = wsrc[f4];
        }
    }

    // ---- coalesced gather: warp w owns rows [32w, 32w+32) ----
    {
        const int myidx = imap[k * PPK + p0 + w * 32 + l];
        const int c16 = l & 15;
        const int rl  = l >> 4;
        const int cin = c16 * 4;
        const int fsw = SWZ(cin);

        #pragma unroll
        for (int q = 0; q < 16; q++) {
            const int src_row = __shfl_sync(0xffffffffu, myidx, 2 * q + rl);
            const int r = w * 32 + 2 * q + rl;
            float4 v = *(const float4*)(in_feats + (size_t)src_row * CIN + cin);
            const int pc = r ^ fsw;
            As[cin + 0][pc] = v.x;
            As[cin + 1][pc] = v.y;
            As[cin + 2][pc] = v.z;
            As[cin + 3][pc] = v.w;
        }
    }
    __syncthreads();

    // ---- register-tiled GEMM: 8 pairs x 8 couts per thread, f32x2 packed ----
    // NEW mapping: tx = tid>>3 (pair group), ty = tid&7 (cout group)
    //   -> a warp covers 4 pair-rows x 8 cout-groups: epilogue red.v4
    //      instructions touch only 4 output rows.
    const int tx = tid >> 3;   // 0..15
    const int ty = tid & 7;    // 0..7

    unsigned long long acc[8][4];
    #pragma unroll
    for (int i = 0; i < 8; i++)
        #pragma unroll
        for (int j = 0; j < 4; j++)
            acc[i][j] = 0ULL;

    const int g0 = WSWZ(2 * ty) * 4;       // physical word offset of w01 group
    const int g1 = WSWZ(2 * ty + 1) * 4;   // physical word offset of w23 group

    #pragma unroll 4
    for (int kk = 0; kk < CIN; kk++) {
        const int fsw = SWZ(kk);
        float4 a0 = *(const float4*)&As[kk][(tx * 4) ^ fsw];
        float4 a1 = *(const float4*)&As[kk][(64 + tx * 4) ^ fsw];
        ulonglong2 w01 = *(const ulonglong2*)&Ws[kk][g0];
        ulonglong2 w23 = *(const ulonglong2*)&Ws[kk][g1];
        unsigned long long wp[4] = {w01.x, w01.y, w23.x, w23.y};

        float av[8] = {a0.x, a0.y, a0.z, a0.w, a1.x, a1.y, a1.z, a1.w};
        unsigned long long ad[8];
        #pragma unroll
        for (int i = 0; i < 8; i++)
            PACK_DUP_F32X2(ad[i], av[i]);

        #pragma unroll
        for (int i = 0; i < 8; i++)
            #pragma unroll
            for (int j = 0; j < 4; j++)
                FMA_F32X2(acc[i][j], ad[i], wp[j]);
    }

    // ---- scatter-add epilogue: 4 rows per warp per instruction ----
    const int obase = k * PPK + p0;
    #pragma unroll
    for (int i = 0; i < 8; i++) {
        const int r = (i < 4) ? (tx * 4 + i) : (64 + tx * 4 + (i - 4));
        const int row = __ldg(omap + obase + r);
        float f[8];
        #pragma unroll
        for (int j = 0; j < 4; j++)
            UNPACK_F32X2(f[2 * j], f[2 * j + 1], acc[i][j]);
        float* dst = out + (size_t)row * COUT + ty * 8;
        red_add_v4(dst,     f[0], f[1], f[2], f[3]);
        red_add_v4(dst + 4, f[4], f[5], f[6], f[7]);
    }
}

// ---------------------------------------------------------------------------
extern "C" void kernel_launch(void* const* d_in, const int* in_sizes, int n_in,
                              void* d_out, int out_size) {
    const float* in_feats = (const float*)d_in[0];
    const float* weights  = (const float*)d_in[1];
    const float* bias     = (const float*)d_in[2];
    const int*   imap     = (const int*)d_in[3];
    const int*   omap     = (const int*)d_in[4];
    float*       out      = (float*)d_out;

    {
        const int total4 = NVOX * COUT / 4;
        init_bias_kernel<<<total4 / 256, 256>>>((float4*)out, (const float4*)bias);
    }

    dim3 grid(PPK / TILE_P, KVOL);
    conv3d_gemm_kernel<<<grid, NTHREADS>>>(in_feats, weights, imap, omap, out);
}

// round 6
// speedup vs baseline: 2.2761x; 1.5743x over previous
#include <cuda_runtime.h>
#include <cuda_bf16.h>
#include <cstdint>

// Problem constants (fixed by the reference)
#define NVOX   131072
#define KVOL   27
#define PPK    65536
#define CIN    64
#define COUT   64
#define NTHREADS 128

// ---------------------------------------------------------------------------
// Pre-split, transposed weights: [KVOL][COUT(n)][CIN(k)] bf16 hi/lo
// ---------------------------------------------------------------------------
__device__ __nv_bfloat16 g_Whi[KVOL * COUT * CIN];
__device__ __nv_bfloat16 g_Wlo[KVOL * COUT * CIN];

// ---------------------------------------------------------------------------
// smem layout: bf16 tiles, 128B per logical row, XOR-swizzled 16B chunks
//   phys = row*128 + ((chunk ^ (row & 7)) << 4) (+ 8 for odd half)
// ---------------------------------------------------------------------------
#define SM_AHI   0                         // 128 rows x 128B = 16384
#define SM_ALO   16384
#define SM_BHI   32768                     // 64 rows x 128B = 8192
#define SM_BLO   40960
#define SM_TOTAL 49152

// ---------------------------------------------------------------------------
// PTX helpers (family-portable: ldmatrix sm_75+, mma bf16 sm_80+, red sm_90)
// ---------------------------------------------------------------------------
__device__ __forceinline__ uint32_t smem_u32(const void* p) {
    uint32_t a;
    asm("{ .reg .u64 t; cvta.to.shared.u64 t, %1; cvt.u32.u64 %0, t; }" : "=r"(a) : "l"(p));
    return a;
}

__device__ __forceinline__ void ldsm_x4(uint32_t r[4], uint32_t addr) {
    asm volatile("ldmatrix.sync.aligned.m8n8.x4.shared.b16 {%0,%1,%2,%3}, [%4];"
                 : "=r"(r[0]), "=r"(r[1]), "=r"(r[2]), "=r"(r[3]) : "r"(addr));
}

__device__ __forceinline__ void mma_bf16(float d[4], const uint32_t a[4], const uint32_t b[2]) {
    asm volatile(
        "mma.sync.aligned.m16n8k16.row.col.f32.bf16.bf16.f32 "
        "{%0,%1,%2,%3}, {%4,%5,%6,%7}, {%8,%9}, {%0,%1,%2,%3};"
        : "+f"(d[0]), "+f"(d[1]), "+f"(d[2]), "+f"(d[3])
        : "r"(a[0]), "r"(a[1]), "r"(a[2]), "r"(a[3]), "r"(b[0]), "r"(b[1]));
}

__device__ __forceinline__ void red_add_v2(float* addr, float a, float b) {
    asm volatile("red.global.add.v2.f32 [%0], {%1, %2};"
                 :: "l"(addr), "f"(a), "f"(b) : "memory");
}

// ---------------------------------------------------------------------------
// Kernel 1: out[n][c] = bias[c]
// ---------------------------------------------------------------------------
__global__ void init_bias_kernel(float4* __restrict__ out, const float4* __restrict__ bias) {
    int i = blockIdx.x * blockDim.x + threadIdx.x;
    out[i] = bias[i & 15];
}

// ---------------------------------------------------------------------------
// Kernel 2: split weights into bf16 hi/lo, transposed to [koff][n][k]
// ---------------------------------------------------------------------------
__global__ void prep_weights_kernel(const float* __restrict__ weights) {
    const int koff = blockIdx.x;
    const float* W = weights + (size_t)koff * CIN * COUT;
    __nv_bfloat16* hi = g_Whi + (size_t)koff * COUT * CIN;
    __nv_bfloat16* lo = g_Wlo + (size_t)koff * COUT * CIN;
    for (int o = threadIdx.x; o < COUT * CIN; o += blockDim.x) {
        const int n = o >> 6, kk = o & 63;
        const float x = W[kk * COUT + n];     // transpose: B[n][k] = W[k][n]
        const __nv_bfloat16 h = __float2bfloat16_rn(x);
        hi[o] = h;
        lo[o] = __float2bfloat16_rn(x - __bfloat162float(h));
    }
}

// ---------------------------------------------------------------------------
// Kernel 3: HMMA GEMM-scatter. One block per (k offset, 128-pair tile).
//   D[128p x 64n] = Ahi*Bhi + Alo*Bhi + Ahi*Blo   (fp32 register accum)
//   Warp w owns M rows [32w, 32w+32) -> 2 m16 tiles; N=64 -> 8 n8 tiles.
// ---------------------------------------------------------------------------
__global__ __launch_bounds__(NTHREADS, 3) void conv3d_tc_kernel(
    const float* __restrict__ in_feats,   // [NVOX, CIN]
    const int*   __restrict__ imap,       // [KVOL, PPK]
    const int*   __restrict__ omap,       // [KVOL, PPK]
    float*       __restrict__ out)        // [NVOX, COUT]
{
    extern __shared__ __align__(128) char smem[];
    const uint32_t smem_base = smem_u32(smem);
    const int tid = threadIdx.x;
    const int w = tid >> 5, l = tid & 31;
    const int k  = blockIdx.y;
    const int p0 = blockIdx.x * 128;

    // ---- B staging: 2 x 8KB bf16 tiles [n][k], swizzled 16B chunks ----
    {
        const uint4* bh = (const uint4*)(g_Whi + (size_t)k * COUT * CIN);
        const uint4* bl = (const uint4*)(g_Wlo + (size_t)k * COUT * CIN);
        #pragma unroll
        for (int i = 0; i < 4; i++) {
            const int u = tid + i * NTHREADS;          // 16B unit 0..511
            const int n = u >> 3, c = u & 7;
            const uint32_t off = n * 128 + ((c ^ (n & 7)) << 4);
            *(uint4*)(smem + SM_BHI + off) = bh[u];
            *(uint4*)(smem + SM_BLO + off) = bl[u];
        }
    }

    // ---- A staging: coalesced gather + bf16 hi/lo split + swizzled STS ----
    {
        const int myidx = imap[k * PPK + p0 + w * 32 + l];
        const int c16 = l & 15, rl = l >> 4;
        const int chunk = c16 >> 1, halfoff = (c16 & 1) * 8;
        #pragma unroll
        for (int q = 0; q < 16; q++) {
            const int src = __shfl_sync(0xffffffffu, myidx, 2 * q + rl);
            const int r = w * 32 + 2 * q + rl;
            float4 v = *(const float4*)(in_feats + (size_t)src * CIN + c16 * 4);

            __nv_bfloat162 h01, h23, l01, l23;
            h01.x = __float2bfloat16_rn(v.x);  h01.y = __float2bfloat16_rn(v.y);
            h23.x = __float2bfloat16_rn(v.z);  h23.y = __float2bfloat16_rn(v.w);
            l01.x = __float2bfloat16_rn(v.x - __bfloat162float(h01.x));
            l01.y = __float2bfloat16_rn(v.y - __bfloat162float(h01.y));
            l23.x = __float2bfloat16_rn(v.z - __bfloat162float(h23.x));
            l23.y = __float2bfloat16_rn(v.w - __bfloat162float(h23.y));

            const uint32_t off = r * 128 + ((chunk ^ (r & 7)) << 4) + halfoff;
            uint2 hv, lv;
            hv.x = *(uint32_t*)&h01;  hv.y = *(uint32_t*)&h23;
            lv.x = *(uint32_t*)&l01;  lv.y = *(uint32_t*)&l23;
            *(uint2*)(smem + SM_AHI + off) = hv;
            *(uint2*)(smem + SM_ALO + off) = lv;
        }
    }
    __syncthreads();

    // ---- per-lane ldmatrix address components ----
    const int lr = l & 7;
    // A x4: matrices {rows+0 kc0, rows+8 kc0, rows+0 kc1, rows+8 kc1}
    const int rA  = w * 32 + ((l >> 3) & 1) * 8 + lr;  // row for t=0 (add 16 for t=1)
    const int gA  = l >> 4;                            // kc offset 0/1
    const int sA  = rA & 7;                            // swizzle key (row&7, +16 invariant)
    // B x4: matrices {tile j n+lr kc0, tile j kc1, tile j+1 kc0, tile j+1 kc1}
    const int nB  = 8 * (l >> 4) + lr;                 // n for jj-group base (add 16*jj)
    const int gB  = (l >> 3) & 1;                      // kc offset 0/1
    const int sB  = nB & 7;

    float d[2][8][4];
    #pragma unroll
    for (int t = 0; t < 2; t++)
        #pragma unroll
        for (int j = 0; j < 8; j++)
            #pragma unroll
            for (int x = 0; x < 4; x++)
                d[t][j][x] = 0.0f;

    // ---- main loop over K (4 x k16 steps) ----
    #pragma unroll
    for (int ks = 0; ks < 4; ks++) {
        const int kcA = 2 * ks + gA;
        const int kcB = 2 * ks + gB;
        const uint32_t offA = rA * 128 + (((kcA) ^ sA) << 4);
        const uint32_t offB0 = nB * 128 + (((kcB) ^ sB) << 4);

        uint32_t ah[2][4], al[2][4];
        ldsm_x4(ah[0], smem_base + SM_AHI + offA);
        ldsm_x4(ah[1], smem_base + SM_AHI + offA + 16 * 128);
        ldsm_x4(al[0], smem_base + SM_ALO + offA);
        ldsm_x4(al[1], smem_base + SM_ALO + offA + 16 * 128);

        // B hi: two passes (Ah*Bh, Al*Bh)
        {
            uint32_t b[8][2];
            #pragma unroll
            for (int jj = 0; jj < 4; jj++) {
                uint32_t rr[4];
                ldsm_x4(rr, smem_base + SM_BHI + offB0 + jj * 16 * 128);
                b[2 * jj][0] = rr[0]; b[2 * jj][1] = rr[1];
                b[2 * jj + 1][0] = rr[2]; b[2 * jj + 1][1] = rr[3];
            }
            #pragma unroll
            for (int t = 0; t < 2; t++)
                #pragma unroll
                for (int j = 0; j < 8; j++)
                    mma_bf16(d[t][j], ah[t], b[j]);
            #pragma unroll
            for (int t = 0; t < 2; t++)
                #pragma unroll
                for (int j = 0; j < 8; j++)
                    mma_bf16(d[t][j], al[t], b[j]);
        }
        // B lo: one pass (Ah*Bl)
        {
            uint32_t b[8][2];
            #pragma unroll
            for (int jj = 0; jj < 4; jj++) {
                uint32_t rr[4];
                ldsm_x4(rr, smem_base + SM_BLO + offB0 + jj * 16 * 128);
                b[2 * jj][0] = rr[0]; b[2 * jj][1] = rr[1];
                b[2 * jj + 1][0] = rr[2]; b[2 * jj + 1][1] = rr[3];
            }
            #pragma unroll
            for (int t = 0; t < 2; t++)
                #pragma unroll
                for (int j = 0; j < 8; j++)
                    mma_bf16(d[t][j], ah[t], b[j]);
        }
    }

    // ---- scatter-add epilogue straight from fragments ----
    // Thread l: rows 32w + 16t + 8h + (l>>2), n = 8j + 2*(l&3).
    // Each red.v2 warp-instr: 8 rows x one 32B sector -> 8 wavefronts.
    {
        const int gid = l >> 2, tig = l & 3;
        const int obase = k * PPK + p0;
        #pragma unroll
        for (int t = 0; t < 2; t++) {
            #pragma unroll
            for (int h = 0; h < 2; h++) {
                const int row = w * 32 + 16 * t + 8 * h + gid;
                const int orow = __ldg(omap + obase + row);
                float* dst = out + (size_t)orow * COUT + 2 * tig;
                #pragma unroll
                for (int j = 0; j < 8; j++)
                    red_add_v2(dst + 8 * j, d[t][j][2 * h], d[t][j][2 * h + 1]);
            }
        }
    }
}

// ---------------------------------------------------------------------------
extern "C" void kernel_launch(void* const* d_in, const int* in_sizes, int n_in,
                              void* d_out, int out_size) {
    const float* in_feats = (const float*)d_in[0];
    const float* weights  = (const float*)d_in[1];
    const float* bias     = (const float*)d_in[2];
    const int*   imap     = (const int*)d_in[3];
    const int*   omap     = (const int*)d_in[4];
    float*       out      = (float*)d_out;

    cudaFuncSetAttribute(conv3d_tc_kernel,
                         cudaFuncAttributeMaxDynamicSharedMemorySize, SM_TOTAL);

    {
        const int total4 = NVOX * COUT / 4;
        init_bias_kernel<<<total4 / 256, 256>>>((float4*)out, (const float4*)bias);
    }

    prep_weights_kernel<<<KVOL, 256>>>(weights);

    dim3 grid(PPK / 128, KVOL);
    conv3d_tc_kernel<<<grid, NTHREADS, SM_TOTAL>>>(in_feats, imap, omap, out);
}

// round 7
// speedup vs baseline: 2.6658x; 1.1712x over previous
#include <cuda_runtime.h>
#include <cuda_bf16.h>
#include <cstdint>

// Problem constants (fixed by the reference)
#define NVOX   131072
#define KVOL   27
#define PPK    65536
#define CIN    64
#define COUT   64
#define NTHREADS 128

// ---------------------------------------------------------------------------
// Pre-split, transposed, COLUMN-PERMUTED weights: [KVOL][64 phys rows][CIN]
// Physical row p = 8j + c holds logical cout n = 16*(j>>1) + 4*(c>>1) + 2*(j&1) + (c&1).
// This makes each MMA thread's 4 values from a tile pair (2jp, 2jp+1) cover
// 4 consecutive couts -> red.v4 epilogue straight from fragments.
// ---------------------------------------------------------------------------
__device__ __nv_bfloat16 g_Whi[KVOL * COUT * CIN];
__device__ __nv_bfloat16 g_Wlo[KVOL * COUT * CIN];

// smem: bf16 tiles, 128B per logical row, XOR-swizzled 16B chunks
#define SM_AHI   0                         // 128 rows x 128B = 16384
#define SM_ALO   16384
#define SM_BHI   32768                     // 64 rows x 128B = 8192
#define SM_BLO   40960
#define SM_TOTAL 49152

// ---------------------------------------------------------------------------
// PTX helpers (family-portable: ldmatrix sm_75+, mma bf16 sm_80+, red sm_90)
// ---------------------------------------------------------------------------
__device__ __forceinline__ uint32_t smem_u32(const void* p) {
    uint32_t a;
    asm("{ .reg .u64 t; cvta.to.shared.u64 t, %1; cvt.u32.u64 %0, t; }" : "=r"(a) : "l"(p));
    return a;
}

__device__ __forceinline__ void ldsm_x4(uint32_t r[4], uint32_t addr) {
    asm volatile("ldmatrix.sync.aligned.m8n8.x4.shared.b16 {%0,%1,%2,%3}, [%4];"
                 : "=r"(r[0]), "=r"(r[1]), "=r"(r[2]), "=r"(r[3]) : "r"(addr));
}

__device__ __forceinline__ void mma_bf16(float d[4], const uint32_t a[4], const uint32_t b[2]) {
    asm volatile(
        "mma.sync.aligned.m16n8k16.row.col.f32.bf16.bf16.f32 "
        "{%0,%1,%2,%3}, {%4,%5,%6,%7}, {%8,%9}, {%0,%1,%2,%3};"
        : "+f"(d[0]), "+f"(d[1]), "+f"(d[2]), "+f"(d[3])
        : "r"(a[0]), "r"(a[1]), "r"(a[2]), "r"(a[3]), "r"(b[0]), "r"(b[1]));
}

__device__ __forceinline__ void red_add_v4(float* addr, float a, float b, float c, float d) {
    asm volatile("red.global.add.v4.f32 [%0], {%1, %2, %3, %4};"
                 :: "l"(addr), "f"(a), "f"(b), "f"(c), "f"(d) : "memory");
}

// ---------------------------------------------------------------------------
// Kernel 1: out[n][c] = bias[c]
// ---------------------------------------------------------------------------
__global__ void init_bias_kernel(float4* __restrict__ out, const float4* __restrict__ bias) {
    int i = blockIdx.x * blockDim.x + threadIdx.x;
    out[i] = bias[i & 15];
}

// ---------------------------------------------------------------------------
// Kernel 2: split weights to bf16 hi/lo, transposed + column-permuted
// ---------------------------------------------------------------------------
__global__ void prep_weights_kernel(const float* __restrict__ weights) {
    const int koff = blockIdx.x;
    const float* W = weights + (size_t)koff * CIN * COUT;
    __nv_bfloat16* hi = g_Whi + (size_t)koff * COUT * CIN;
    __nv_bfloat16* lo = g_Wlo + (size_t)koff * COUT * CIN;
    for (int o = threadIdx.x; o < COUT * CIN; o += blockDim.x) {
        const int p = o >> 6, kk = o & 63;
        const int j = p >> 3, c = p & 7;
        const int n = 16 * (j >> 1) + 4 * (c >> 1) + 2 * (j & 1) + (c & 1);
        const float x = W[kk * COUT + n];     // transpose + permute
        const __nv_bfloat16 h = __float2bfloat16_rn(x);
        hi[o] = h;
        lo[o] = __float2bfloat16_rn(x - __bfloat162float(h));
    }
}

// ---------------------------------------------------------------------------
// Kernel 3: HMMA GEMM-scatter. One block per (k offset, 128-pair tile).
//   D[128p x 64n] = Ahi*Bhi + Alo*Bhi + Ahi*Blo   (fp32 register accum)
// ---------------------------------------------------------------------------
__global__ __launch_bounds__(NTHREADS, 3) void conv3d_tc_kernel(
    const float* __restrict__ in_feats,   // [NVOX, CIN]
    const int*   __restrict__ imap,       // [KVOL, PPK]
    const int*   __restrict__ omap,       // [KVOL, PPK]
    float*       __restrict__ out)        // [NVOX, COUT]
{
    extern __shared__ __align__(128) char smem[];
    const uint32_t smem_base = smem_u32(smem);
    const int tid = threadIdx.x;
    const int w = tid >> 5, l = tid & 31;
    const int k  = blockIdx.y;
    const int p0 = blockIdx.x * 128;

    // ---- B staging: 2 x 8KB bf16 tiles [phys n][k], swizzled 16B chunks ----
    {
        const uint4* bh = (const uint4*)(g_Whi + (size_t)k * COUT * CIN);
        const uint4* bl = (const uint4*)(g_Wlo + (size_t)k * COUT * CIN);
        #pragma unroll
        for (int i = 0; i < 4; i++) {
            const int u = tid + i * NTHREADS;          // 16B unit 0..511
            const int n = u >> 3, c = u & 7;
            const uint32_t off = n * 128 + ((c ^ (n & 7)) << 4);
            *(uint4*)(smem + SM_BHI + off) = bh[u];
            *(uint4*)(smem + SM_BLO + off) = bl[u];
        }
    }

    // ---- A staging: coalesced gather + bf16 hi/lo split + swizzled STS ----
    {
        const int myidx = imap[k * PPK + p0 + w * 32 + l];
        const int c16 = l & 15, rl = l >> 4;
        const int chunk = c16 >> 1, halfoff = (c16 & 1) * 8;
        #pragma unroll
        for (int q = 0; q < 16; q++) {
            const int src = __shfl_sync(0xffffffffu, myidx, 2 * q + rl);
            const int r = w * 32 + 2 * q + rl;
            float4 v = *(const float4*)(in_feats + (size_t)src * CIN + c16 * 4);

            __nv_bfloat162 h01, h23, l01, l23;
            h01.x = __float2bfloat16_rn(v.x);  h01.y = __float2bfloat16_rn(v.y);
            h23.x = __float2bfloat16_rn(v.z);  h23.y = __float2bfloat16_rn(v.w);
            l01.x = __float2bfloat16_rn(v.x - __bfloat162float(h01.x));
            l01.y = __float2bfloat16_rn(v.y - __bfloat162float(h01.y));
            l23.x = __float2bfloat16_rn(v.z - __bfloat162float(h23.x));
            l23.y = __float2bfloat16_rn(v.w - __bfloat162float(h23.y));

            const uint32_t off = r * 128 + ((chunk ^ (r & 7)) << 4) + halfoff;
            uint2 hv, lv;
            hv.x = *(uint32_t*)&h01;  hv.y = *(uint32_t*)&h23;
            lv.x = *(uint32_t*)&l01;  lv.y = *(uint32_t*)&l23;
            *(uint2*)(smem + SM_AHI + off) = hv;
            *(uint2*)(smem + SM_ALO + off) = lv;
        }
    }

    // ---- prefetch omap rows (hidden behind MMA work) ----
    const int gid = l >> 2, tig = l & 3;
    int orow[2][2];
    {
        const int obase = k * PPK + p0 + w * 32 + gid;
        #pragma unroll
        for (int t = 0; t < 2; t++)
            #pragma unroll
            for (int h = 0; h < 2; h++)
                orow[t][h] = __ldg(omap + obase + 16 * t + 8 * h);
    }

    __syncthreads();

    // ---- per-lane ldmatrix address components ----
    const int lr = l & 7;
    const int rA  = w * 32 + ((l >> 3) & 1) * 8 + lr;  // A row for t=0 (+16 for t=1)
    const int gA  = l >> 4;                            // A kc offset 0/1
    const int sA  = rA & 7;
    const int nB  = 8 * (l >> 4) + lr;                 // B row for jj base (+16*jj)
    const int gB  = (l >> 3) & 1;                      // B kc offset 0/1
    const int sB  = nB & 7;

    float d[2][8][4];
    #pragma unroll
    for (int t = 0; t < 2; t++)
        #pragma unroll
        for (int j = 0; j < 8; j++)
            #pragma unroll
            for (int x = 0; x < 4; x++)
                d[t][j][x] = 0.0f;

    // ---- main loop over K (4 x k16 steps) ----
    #pragma unroll
    for (int ks = 0; ks < 4; ks++) {
        const int kcA = 2 * ks + gA;
        const int kcB = 2 * ks + gB;
        const uint32_t offA  = rA * 128 + ((kcA ^ sA) << 4);
        const uint32_t offB0 = nB * 128 + ((kcB ^ sB) << 4);

        uint32_t ah[2][4], al[2][4];
        ldsm_x4(ah[0], smem_base + SM_AHI + offA);
        ldsm_x4(ah[1], smem_base + SM_AHI + offA + 16 * 128);
        ldsm_x4(al[0], smem_base + SM_ALO + offA);
        ldsm_x4(al[1], smem_base + SM_ALO + offA + 16 * 128);

        // B hi: two passes (Ah*Bh, Al*Bh)
        {
            uint32_t b[8][2];
            #pragma unroll
            for (int jj = 0; jj < 4; jj++) {
                uint32_t rr[4];
                ldsm_x4(rr, smem_base + SM_BHI + offB0 + jj * 16 * 128);
                b[2 * jj][0] = rr[0]; b[2 * jj][1] = rr[1];
                b[2 * jj + 1][0] = rr[2]; b[2 * jj + 1][1] = rr[3];
            }
            #pragma unroll
            for (int t = 0; t < 2; t++)
                #pragma unroll
                for (int j = 0; j < 8; j++)
                    mma_bf16(d[t][j], ah[t], b[j]);
            #pragma unroll
            for (int t = 0; t < 2; t++)
                #pragma unroll
                for (int j = 0; j < 8; j++)
                    mma_bf16(d[t][j], al[t], b[j]);
        }
        // B lo: one pass (Ah*Bl)
        {
            uint32_t b[8][2];
            #pragma unroll
            for (int jj = 0; jj < 4; jj++) {
                uint32_t rr[4];
                ldsm_x4(rr, smem_base + SM_BLO + offB0 + jj * 16 * 128);
                b[2 * jj][0] = rr[0]; b[2 * jj][1] = rr[1];
                b[2 * jj + 1][0] = rr[2]; b[2 * jj + 1][1] = rr[3];
            }
            #pragma unroll
            for (int t = 0; t < 2; t++)
                #pragma unroll
                for (int j = 0; j < 8; j++)
                    mma_bf16(d[t][j], ah[t], b[j]);
        }
    }

    // ---- scatter-add epilogue: red.v4 straight from fragments ----
    // Column permutation makes (d[2jp][2h],d[2jp][2h+1],d[2jp+1][2h],d[2jp+1][2h+1])
    // cover logical couts 16jp+4tig .. +3. Per instr: 8 rows x 64B -> 8 wf.
    #pragma unroll
    for (int t = 0; t < 2; t++) {
        #pragma unroll
        for (int h = 0; h < 2; h++) {
            float* dst = out + (size_t)orow[t][h] * COUT + 4 * tig;
            #pragma unroll
            for (int jp = 0; jp < 4; jp++)
                red_add_v4(dst + 16 * jp,
                           d[t][2 * jp][2 * h],     d[t][2 * jp][2 * h + 1],
                           d[t][2 * jp + 1][2 * h], d[t][2 * jp + 1][2 * h + 1]);
        }
    }
}

// ---------------------------------------------------------------------------
extern "C" void kernel_launch(void* const* d_in, const int* in_sizes, int n_in,
                              void* d_out, int out_size) {
    const float* in_feats = (const float*)d_in[0];
    const float* weights  = (const float*)d_in[1];
    const float* bias     = (const float*)d_in[2];
    const int*   imap     = (const int*)d_in[3];
    const int*   omap     = (const int*)d_in[4];
    float*       out      = (float*)d_out;

    cudaFuncSetAttribute(conv3d_tc_kernel,
                         cudaFuncAttributeMaxDynamicSharedMemorySize, SM_TOTAL);

    {
        const int total4 = NVOX * COUT / 4;
        init_bias_kernel<<<total4 / 256, 256>>>((float4*)out, (const float4*)bias);
    }

    prep_weights_kernel<<<KVOL, 256>>>(weights);

    dim3 grid(PPK / 128, KVOL);
    conv3d_tc_kernel<<<grid, NTHREADS, SM_TOTAL>>>(in_feats, imap, omap, out);
}

// round 8
// speedup vs baseline: 3.5788x; 1.3425x over previous
#include <cuda_runtime.h>
#include <cuda_bf16.h>
#include <cuda_fp16.h>
#include <cstdint>

// Problem constants (fixed by the reference)
#define NVOX   131072
#define KVOL   27
#define PPK    65536
#define CIN    64
#define COUT   64
#define NTHREADS 128

// ---------------------------------------------------------------------------
// Pre-converted, transposed, COLUMN-PERMUTED fp16 weights: [KVOL][64 rows][CIN]
// Physical row p = 8j + c holds logical cout n = 16*(j>>1) + 4*(c>>1) + 2*(j&1) + (c&1)
// -> each MMA thread's 4 values from a tile pair cover 4 consecutive couts
//    (red.v4 epilogue straight from fragments).
// ---------------------------------------------------------------------------
__device__ __half g_Wh[KVOL * COUT * CIN];

// smem: fp16 tiles, 128B per logical row, XOR-swizzled 16B chunks
#define SM_A     0                         // 128 rows x 128B = 16384
#define SM_B     16384                     // 64 rows x 128B = 8192
#define SM_TOTAL 24576

// ---------------------------------------------------------------------------
// PTX helpers (family-portable: ldmatrix sm_75+, mma fp16 sm_70+, red sm_90)
// ---------------------------------------------------------------------------
__device__ __forceinline__ uint32_t smem_u32(const void* p) {
    uint32_t a;
    asm("{ .reg .u64 t; cvta.to.shared.u64 t, %1; cvt.u32.u64 %0, t; }" : "=r"(a) : "l"(p));
    return a;
}

__device__ __forceinline__ void ldsm_x4(uint32_t r[4], uint32_t addr) {
    asm volatile("ldmatrix.sync.aligned.m8n8.x4.shared.b16 {%0,%1,%2,%3}, [%4];"
                 : "=r"(r[0]), "=r"(r[1]), "=r"(r[2]), "=r"(r[3]) : "r"(addr));
}

__device__ __forceinline__ void mma_fp16(float d[4], const uint32_t a[4], const uint32_t b[2]) {
    asm volatile(
        "mma.sync.aligned.m16n8k16.row.col.f32.f16.f16.f32 "
        "{%0,%1,%2,%3}, {%4,%5,%6,%7}, {%8,%9}, {%0,%1,%2,%3};"
        : "+f"(d[0]), "+f"(d[1]), "+f"(d[2]), "+f"(d[3])
        : "r"(a[0]), "r"(a[1]), "r"(a[2]), "r"(a[3]), "r"(b[0]), "r"(b[1]));
}

__device__ __forceinline__ void red_add_v4(float* addr, float a, float b, float c, float d) {
    asm volatile("red.global.add.v4.f32 [%0], {%1, %2, %3, %4};"
                 :: "l"(addr), "f"(a), "f"(b), "f"(c), "f"(d) : "memory");
}

// ---------------------------------------------------------------------------
// Kernel 1: out[n][c] = bias[c]
// ---------------------------------------------------------------------------
__global__ void init_bias_kernel(float4* __restrict__ out, const float4* __restrict__ bias) {
    int i = blockIdx.x * blockDim.x + threadIdx.x;
    out[i] = bias[i & 15];
}

// ---------------------------------------------------------------------------
// Kernel 2: weights -> fp16, transposed + column-permuted
// ---------------------------------------------------------------------------
__global__ void prep_weights_kernel(const float* __restrict__ weights) {
    const int koff = blockIdx.x;
    const float* W = weights + (size_t)koff * CIN * COUT;
    __half* wh = g_Wh + (size_t)koff * COUT * CIN;
    for (int o = threadIdx.x; o < COUT * CIN; o += blockDim.x) {
        const int p = o >> 6, kk = o & 63;
        const int j = p >> 3, c = p & 7;
        const int n = 16 * (j >> 1) + 4 * (c >> 1) + 2 * (j & 1) + (c & 1);
        wh[o] = __float2half_rn(W[kk * COUT + n]);   // transpose + permute
    }
}

// ---------------------------------------------------------------------------
// Kernel 3: fp16 HMMA GEMM-scatter. One block per (k offset, 128-pair tile).
//   D[128p x 64n] = A_fp16 * B_fp16  (fp32 register accum; single pass)
// ---------------------------------------------------------------------------
__global__ __launch_bounds__(NTHREADS, 4) void conv3d_tc_kernel(
    const float* __restrict__ in_feats,   // [NVOX, CIN]
    const int*   __restrict__ imap,       // [KVOL, PPK]
    const int*   __restrict__ omap,       // [KVOL, PPK]
    float*       __restrict__ out)        // [NVOX, COUT]
{
    extern __shared__ __align__(128) char smem[];
    const uint32_t smem_base = smem_u32(smem);
    const int tid = threadIdx.x;
    const int w = tid >> 5, l = tid & 31;
    const int k  = blockIdx.y;
    const int p0 = blockIdx.x * 128;

    // ---- B staging: 8KB fp16 tile [phys n][k], swizzled 16B chunks ----
    {
        const uint4* bh = (const uint4*)(g_Wh + (size_t)k * COUT * CIN);
        #pragma unroll
        for (int i = 0; i < 4; i++) {
            const int u = tid + i * NTHREADS;          // 16B unit 0..511
            const int n = u >> 3, c = u & 7;
            const uint32_t off = n * 128 + ((c ^ (n & 7)) << 4);
            *(uint4*)(smem + SM_B + off) = bh[u];
        }
    }

    // ---- A staging: coalesced gather + fp16 convert + swizzled STS ----
    {
        const int myidx = imap[k * PPK + p0 + w * 32 + l];
        const int c16 = l & 15, rl = l >> 4;
        const int chunk = c16 >> 1, halfoff = (c16 & 1) * 8;
        #pragma unroll
        for (int q = 0; q < 16; q++) {
            const int src = __shfl_sync(0xffffffffu, myidx, 2 * q + rl);
            const int r = w * 32 + 2 * q + rl;
            float4 v = *(const float4*)(in_feats + (size_t)src * CIN + c16 * 4);

            __half2 h01 = make_half2(__float2half_rn(v.x), __float2half_rn(v.y));
            __half2 h23 = make_half2(__float2half_rn(v.z), __float2half_rn(v.w));

            const uint32_t off = r * 128 + ((chunk ^ (r & 7)) << 4) + halfoff;
            uint2 hv;
            hv.x = *(uint32_t*)&h01;  hv.y = *(uint32_t*)&h23;
            *(uint2*)(smem + SM_A + off) = hv;
        }
    }

    // ---- prefetch omap rows (hidden behind MMA work) ----
    const int gid = l >> 2, tig = l & 3;
    int orow[2][2];
    {
        const int obase = k * PPK + p0 + w * 32 + gid;
        #pragma unroll
        for (int t = 0; t < 2; t++)
            #pragma unroll
            for (int h = 0; h < 2; h++)
                orow[t][h] = __ldg(omap + obase + 16 * t + 8 * h);
    }

    __syncthreads();

    // ---- per-lane ldmatrix address components ----
    const int lr = l & 7;
    const int rA  = w * 32 + ((l >> 3) & 1) * 8 + lr;  // A row for t=0 (+16 for t=1)
    const int gA  = l >> 4;                            // A kc offset 0/1
    const int sA  = rA & 7;
    const int nB  = 8 * (l >> 4) + lr;                 // B row for jj base (+16*jj)
    const int gB  = (l >> 3) & 1;                      // B kc offset 0/1
    const int sB  = nB & 7;

    float d[2][8][4];
    #pragma unroll
    for (int t = 0; t < 2; t++)
        #pragma unroll
        for (int j = 0; j < 8; j++)
            #pragma unroll
            for (int x = 0; x < 4; x++)
                d[t][j][x] = 0.0f;

    // ---- main loop over K (4 x k16 steps), single fp16 pass ----
    #pragma unroll
    for (int ks = 0; ks < 4; ks++) {
        const int kcA = 2 * ks + gA;
        const int kcB = 2 * ks + gB;
        const uint32_t offA  = rA * 128 + ((kcA ^ sA) << 4);
        const uint32_t offB0 = nB * 128 + ((kcB ^ sB) << 4);

        uint32_t a[2][4];
        ldsm_x4(a[0], smem_base + SM_A + offA);
        ldsm_x4(a[1], smem_base + SM_A + offA + 16 * 128);

        uint32_t b[8][2];
        #pragma unroll
        for (int jj = 0; jj < 4; jj++) {
            uint32_t rr[4];
            ldsm_x4(rr, smem_base + SM_B + offB0 + jj * 16 * 128);
            b[2 * jj][0] = rr[0]; b[2 * jj][1] = rr[1];
            b[2 * jj + 1][0] = rr[2]; b[2 * jj + 1][1] = rr[3];
        }

        #pragma unroll
        for (int t = 0; t < 2; t++)
            #pragma unroll
            for (int j = 0; j < 8; j++)
                mma_fp16(d[t][j], a[t], b[j]);
    }

    // ---- scatter-add epilogue: red.v4 straight from fragments ----
    #pragma unroll
    for (int t = 0; t < 2; t++) {
        #pragma unroll
        for (int h = 0; h < 2; h++) {
            float* dst = out + (size_t)orow[t][h] * COUT + 4 * tig;
            #pragma unroll
            for (int jp = 0; jp < 4; jp++)
                red_add_v4(dst + 16 * jp,
                           d[t][2 * jp][2 * h],     d[t][2 * jp][2 * h + 1],
                           d[t][2 * jp + 1][2 * h], d[t][2 * jp + 1][2 * h + 1]);
        }
    }
}

// ---------------------------------------------------------------------------
extern "C" void kernel_launch(void* const* d_in, const int* in_sizes, int n_in,
                              void* d_out, int out_size) {
    const float* in_feats = (const float*)d_in[0];
    const float* weights  = (const float*)d_in[1];
    const float* bias     = (const float*)d_in[2];
    const int*   imap     = (const int*)d_in[3];
    const int*   omap     = (const int*)d_in[4];
    float*       out      = (float*)d_out;

    cudaFuncSetAttribute(conv3d_tc_kernel,
                         cudaFuncAttributeMaxDynamicSharedMemorySize, SM_TOTAL);

    {
        const int total4 = NVOX * COUT / 4;
        init_bias_kernel<<<total4 / 256, 256>>>((float4*)out, (const float4*)bias);
    }

    prep_weights_kernel<<<KVOL, 256>>>(weights);

    dim3 grid(PPK / 128, KVOL);
    conv3d_tc_kernel<<<grid, NTHREADS, SM_TOTAL>>>(in_feats, imap, omap, out);
}